// round 3
// baseline (speedup 1.0000x reference)
#include <cuda_runtime.h>
#include <cstdint>

typedef unsigned long long ULL;

#define B_   64
#define S_   1024
#define I_   1024
#define H_   1024
#define SH_  (S_ * H_)   // 1048576

// ---- packed f32x2 helpers (B300 / sm_103a only) ----
__device__ __forceinline__ void fma2(ULL& d, ULL a, ULL b) {
    asm("fma.rn.f32x2 %0, %1, %2, %0;" : "+l"(d) : "l"(a), "l"(b));
}
__device__ __forceinline__ ULL dup2(float x) {
    ULL r;
    asm("mov.b64 %0, {%1, %1};" : "=l"(r) : "f"(x));
    return r;
}
__device__ __forceinline__ float pairsum(ULL v) {
    union { ULL u; float2 f; } t;
    t.u = v;
    return t.f.x + t.f.y;
}

// ============================================================================
// Kernel 1: wx[m, n] = sum_k x[m,k] * Wih[n,k] + Wih_b[n]
// M = B*S = 65536, N = H = 1024, K = I = 1024
// Writes directly into the y region of d_out (y layout [B,S,H] == [M,H]).
// ============================================================================
__global__ __launch_bounds__(256, 2)
void wx_gemm(const float* __restrict__ A,      // x  [M, K]
             const float* __restrict__ W,      // Wih_w [N, K]
             const float* __restrict__ bias,   // [N]
             float* __restrict__ C)            // y  [M, N]
{
    __shared__ float As[8][128];
    __shared__ float Bs[8][128];

    const int tid = threadIdx.x;
    const int m0 = blockIdx.y * 128;
    const int n0 = blockIdx.x * 128;

    const int lrow = tid >> 1;         // 0..127
    const int lk4  = (tid & 1) * 4;    // 0 or 4

    const float* Aptr = A + (size_t)(m0 + lrow) * I_ + lk4;
    const float* Wptr = W + (size_t)(n0 + lrow) * I_ + lk4;

    const int tx = tid & 15;           // n-direction, 0..15
    const int ty = tid >> 4;           // m-direction, 0..15

    ULL acc[8][4];
#pragma unroll
    for (int i = 0; i < 8; i++)
#pragma unroll
        for (int j = 0; j < 4; j++) acc[i][j] = 0ull;

    for (int k0 = 0; k0 < I_; k0 += 8) {
        float4 av = *(const float4*)(Aptr + k0);
        float4 wv = *(const float4*)(Wptr + k0);
        __syncthreads();
        As[lk4 + 0][lrow] = av.x;
        As[lk4 + 1][lrow] = av.y;
        As[lk4 + 2][lrow] = av.z;
        As[lk4 + 3][lrow] = av.w;
        Bs[lk4 + 0][lrow] = wv.x;
        Bs[lk4 + 1][lrow] = wv.y;
        Bs[lk4 + 2][lrow] = wv.z;
        Bs[lk4 + 3][lrow] = wv.w;
        __syncthreads();

#pragma unroll
        for (int kk = 0; kk < 8; kk++) {
            float4 a0 = *(const float4*)&As[kk][ty * 8];
            float4 a1 = *(const float4*)&As[kk][ty * 8 + 4];
            const ULL* bp = (const ULL*)&Bs[kk][tx * 8];
            ULL b2[4];
            b2[0] = bp[0]; b2[1] = bp[1]; b2[2] = bp[2]; b2[3] = bp[3];
            float a[8] = {a0.x, a0.y, a0.z, a0.w, a1.x, a1.y, a1.z, a1.w};
#pragma unroll
            for (int i = 0; i < 8; i++) {
                ULL ad = dup2(a[i]);
#pragma unroll
                for (int j = 0; j < 4; j++) fma2(acc[i][j], ad, b2[j]);
            }
        }
    }

    const float4* bp4 = (const float4*)(bias + n0 + tx * 8);
    float4 bv0 = bp4[0];
    float4 bv1 = bp4[1];
    float* Cp = C + (size_t)(m0 + ty * 8) * H_ + n0 + tx * 8;
#pragma unroll
    for (int i = 0; i < 8; i++) {
        union { ULL u; float2 f; } t0, t1, t2, t3;
        t0.u = acc[i][0]; t1.u = acc[i][1]; t2.u = acc[i][2]; t3.u = acc[i][3];
        float4 o0 = make_float4(t0.f.x + bv0.x, t0.f.y + bv0.y,
                                t1.f.x + bv0.z, t1.f.y + bv0.w);
        float4 o1 = make_float4(t2.f.x + bv1.x, t2.f.y + bv1.y,
                                t3.f.x + bv1.z, t3.f.y + bv1.w);
        *(float4*)(Cp + (size_t)i * H_)     = o0;
        *(float4*)(Cp + (size_t)i * H_ + 4) = o1;
    }
}

// ============================================================================
// Software grid-wide barrier (all 128 CTAs are co-resident: 128 < 148 SMs).
// Counter + generation; generation is monotonic across graph replays.
// ============================================================================
__device__ unsigned g_bar_count = 0;
__device__ volatile unsigned g_bar_gen = 0;

__device__ __forceinline__ void grid_barrier(unsigned nblocks) {
    __syncthreads();
    if (threadIdx.x == 0) {
        __threadfence();                       // flush this CTA's y-writes
        unsigned gen = g_bar_gen;
        if (atomicAdd(&g_bar_count, 1) == nblocks - 1) {
            g_bar_count = 0;
            __threadfence();
            g_bar_gen = gen + 1;               // release
        } else {
            while (g_bar_gen == gen) { }       // spin
        }
    }
    __syncthreads();
}

// ============================================================================
// Kernel 2: persistent recurrence. All 1024 steps in one launch.
//   y[b, s, f] = tanh( wx(in place) + sum_k Whh[f,k] * h_prev[b,k] + Whh_b[f] )
// Grid: (32 feature tiles of 32) x (4 batch groups of 16); 256 threads.
// ============================================================================
__global__ __launch_bounds__(256, 1)
void rnn_persistent(const float* __restrict__ h0,
                    const float* __restrict__ Whh,
                    const float* __restrict__ bias,
                    float* __restrict__ y,       // [B, S, H], wx preloaded
                    float* __restrict__ hlast)   // [B, H]
{
    __shared__ float hs[16 * 132];          // 16 batches x 128 k (+pad)
    __shared__ float red[8][32][33];        // per-warp reduction scratch

    const int tid  = threadIdx.x;
    const int w    = tid >> 5;
    const int lane = tid & 31;
    const int ftile = blockIdx.x * 32;
    const int bg    = blockIdx.y * 16;
    const int f0    = ftile + w * 4;
    const unsigned NB = gridDim.x * gridDim.y;   // 128

    for (int s = 0; s < S_; s++) {
        const float* hprev = (s == 0) ? h0 : (y + (size_t)(s - 1) * H_);
        const int hstride  = (s == 0) ? H_ : SH_;
        float* y_s = y + (size_t)s * H_;

        ULL acc[4][16];
#pragma unroll
        for (int f = 0; f < 4; f++)
#pragma unroll
            for (int b = 0; b < 16; b++) acc[f][b] = 0ull;

        for (int chunk = 0; chunk < 8; chunk++) {
            const int kc = chunk * 128;
            __syncthreads();   // previous chunk's reads of hs complete
#pragma unroll
            for (int r = 0; r < 2; r++) {
                int p  = tid + 256 * r;           // 0..511 float4 slots
                int b  = p >> 5;
                int c4 = p & 31;
                // L2 load (bypass L1): h rows were written by other SMs
                float4 v = __ldcg((const float4*)(hprev +
                           (size_t)(bg + b) * hstride + kc + c4 * 4));
                *(float4*)&hs[b * 132 + c4 * 4] = v;
            }
            __syncthreads();

            const float* wbase = Whh + kc + lane * 4;
            ulonglong2 w2[4];
#pragma unroll
            for (int f = 0; f < 4; f++)
                w2[f] = *(const ulonglong2*)(wbase + (size_t)(f0 + f) * H_);

#pragma unroll
            for (int b = 0; b < 16; b++) {
                ulonglong2 hv = *(const ulonglong2*)&hs[b * 132 + lane * 4];
#pragma unroll
                for (int f = 0; f < 4; f++) {
                    fma2(acc[f][b], hv.x, w2[f].x);
                    fma2(acc[f][b], hv.y, w2[f].y);
                }
            }
        }

        // ---- reduce 32 lane K-slices; two passes of 32 outputs each ----
#pragma unroll
        for (int p = 0; p < 2; p++) {
            __syncwarp();
#pragma unroll
            for (int fl = 0; fl < 2; fl++) {
                int f = p * 2 + fl;
#pragma unroll
                for (int b = 0; b < 16; b++)
                    red[w][fl * 16 + b][lane] = pairsum(acc[f][b]);
            }
            __syncwarp();
            float sum = 0.0f;
#pragma unroll
            for (int j = 0; j < 32; j++) sum += red[w][lane][j];

            const int o   = p * 32 + lane;        // 0..63
            const int fl  = o >> 4;               // 0..3
            const int bl  = o & 15;
            const int fg  = ftile + w * 4 + fl;
            const int bgl = bg + bl;
            float* yp = y_s + (size_t)bgl * SH_ + fg;
            float val = tanhf(*yp + sum + bias[fg]);
            *yp = val;
            if (s == S_ - 1) hlast[(size_t)bgl * H_ + fg] = val;
        }

        grid_barrier(NB);   // y[:,s,:] visible chip-wide before step s+1
    }
}

// ============================================================================
// Launch: wx GEMM + one persistent kernel. 2 graph nodes total.
// Inputs (metadata order): x, h, Wih_w, Wih_b, Whh_w, Whh_b.
// Output: y [B,S,H] followed by h_last [B,H].
// ============================================================================
extern "C" void kernel_launch(void* const* d_in, const int* in_sizes, int n_in,
                              void* d_out, int out_size)
{
    const float* x     = (const float*)d_in[0];
    const float* h0    = (const float*)d_in[1];
    const float* Wih_w = (const float*)d_in[2];
    const float* Wih_b = (const float*)d_in[3];
    const float* Whh_w = (const float*)d_in[4];
    const float* Whh_b = (const float*)d_in[5];

    float* y     = (float*)d_out;
    float* hlast = y + (size_t)B_ * S_ * H_;

    wx_gemm<<<dim3(8, 512), 256>>>(x, Wih_w, Wih_b, y);
    rnn_persistent<<<dim3(32, 4), 256>>>(h0, Whh_w, Whh_b, y, hlast);
}

// round 4
// speedup vs baseline: 1.1973x; 1.1973x over previous
#include <cuda_runtime.h>
#include <cstdint>

typedef unsigned long long ULL;

#define B_   64
#define S_   1024
#define I_   1024
#define H_   1024
#define SH_  (S_ * H_)   // 1048576

// ---- packed f32x2 helpers (B300 / sm_103a only) ----
__device__ __forceinline__ void fma2(ULL& d, ULL a, ULL b) {
    asm("fma.rn.f32x2 %0, %1, %2, %0;" : "+l"(d) : "l"(a), "l"(b));
}
__device__ __forceinline__ ULL dup2(float x) {
    ULL r;
    asm("mov.b64 %0, {%1, %1};" : "=l"(r) : "f"(x));
    return r;
}
__device__ __forceinline__ float pairsum(ULL v) {
    union { ULL u; float2 f; } t;
    t.u = v;
    return t.f.x + t.f.y;
}

// ============================================================================
// Kernel 1: wx[m, n] = sum_k x[m,k] * Wih[n,k] + Wih_b[n]   (unchanged)
// ============================================================================
__global__ __launch_bounds__(256, 2)
void wx_gemm(const float* __restrict__ A,
             const float* __restrict__ W,
             const float* __restrict__ bias,
             float* __restrict__ C)
{
    __shared__ float As[8][128];
    __shared__ float Bs[8][128];

    const int tid = threadIdx.x;
    const int m0 = blockIdx.y * 128;
    const int n0 = blockIdx.x * 128;

    const int lrow = tid >> 1;
    const int lk4  = (tid & 1) * 4;

    const float* Aptr = A + (size_t)(m0 + lrow) * I_ + lk4;
    const float* Wptr = W + (size_t)(n0 + lrow) * I_ + lk4;

    const int tx = tid & 15;
    const int ty = tid >> 4;

    ULL acc[8][4];
#pragma unroll
    for (int i = 0; i < 8; i++)
#pragma unroll
        for (int j = 0; j < 4; j++) acc[i][j] = 0ull;

    for (int k0 = 0; k0 < I_; k0 += 8) {
        float4 av = *(const float4*)(Aptr + k0);
        float4 wv = *(const float4*)(Wptr + k0);
        __syncthreads();
        As[lk4 + 0][lrow] = av.x;
        As[lk4 + 1][lrow] = av.y;
        As[lk4 + 2][lrow] = av.z;
        As[lk4 + 3][lrow] = av.w;
        Bs[lk4 + 0][lrow] = wv.x;
        Bs[lk4 + 1][lrow] = wv.y;
        Bs[lk4 + 2][lrow] = wv.z;
        Bs[lk4 + 3][lrow] = wv.w;
        __syncthreads();

#pragma unroll
        for (int kk = 0; kk < 8; kk++) {
            float4 a0 = *(const float4*)&As[kk][ty * 8];
            float4 a1 = *(const float4*)&As[kk][ty * 8 + 4];
            const ULL* bp = (const ULL*)&Bs[kk][tx * 8];
            ULL b2[4];
            b2[0] = bp[0]; b2[1] = bp[1]; b2[2] = bp[2]; b2[3] = bp[3];
            float a[8] = {a0.x, a0.y, a0.z, a0.w, a1.x, a1.y, a1.z, a1.w};
#pragma unroll
            for (int i = 0; i < 8; i++) {
                ULL ad = dup2(a[i]);
#pragma unroll
                for (int j = 0; j < 4; j++) fma2(acc[i][j], ad, b2[j]);
            }
        }
    }

    const float4* bp4 = (const float4*)(bias + n0 + tx * 8);
    float4 bv0 = bp4[0];
    float4 bv1 = bp4[1];
    float* Cp = C + (size_t)(m0 + ty * 8) * H_ + n0 + tx * 8;
#pragma unroll
    for (int i = 0; i < 8; i++) {
        union { ULL u; float2 f; } t0, t1, t2, t3;
        t0.u = acc[i][0]; t1.u = acc[i][1]; t2.u = acc[i][2]; t3.u = acc[i][3];
        float4 o0 = make_float4(t0.f.x + bv0.x, t0.f.y + bv0.y,
                                t1.f.x + bv0.z, t1.f.y + bv0.w);
        float4 o1 = make_float4(t2.f.x + bv1.x, t2.f.y + bv1.y,
                                t3.f.x + bv1.z, t3.f.y + bv1.w);
        *(float4*)(Cp + (size_t)i * H_)     = o0;
        *(float4*)(Cp + (size_t)i * H_ + 4) = o1;
    }
}

// ============================================================================
// Grid-wide barrier via acquire/release atomics (128 co-resident CTAs).
// gen only advances when ALL CTAs have arrived, so a late-starting CTA always
// reads the pre-release generation. Monotonic across graph replays.
// ============================================================================
__device__ unsigned g_bar_count = 0;
__device__ unsigned g_bar_gen   = 0;

__device__ __forceinline__ void grid_barrier(unsigned nblocks) {
    __syncthreads();
    if (threadIdx.x == 0) {
        unsigned gen;
        asm volatile("ld.global.acquire.gpu.u32 %0, [%1];"
                     : "=r"(gen) : "l"(&g_bar_gen));
        unsigned prev;
        asm volatile("atom.global.release.gpu.add.u32 %0, [%1], %2;"
                     : "=r"(prev) : "l"(&g_bar_count), "r"(1u));
        if (prev == nblocks - 1) {
            asm volatile("st.global.relaxed.gpu.u32 [%0], %1;"
                         :: "l"(&g_bar_count), "r"(0u));
            asm volatile("st.global.release.gpu.u32 [%0], %1;"
                         :: "l"(&g_bar_gen), "r"(gen + 1u));
        } else {
            unsigned cur;
            do {
                asm volatile("ld.global.acquire.gpu.u32 %0, [%1];"
                             : "=r"(cur) : "l"(&g_bar_gen));
            } while (cur == gen);
        }
    }
    __syncthreads();
}

// ============================================================================
// Kernel 2: persistent recurrence, Whh resident in smem.
// Dynamic smem layout (196608 B):
//   wsm [32][1024]  float  (131072 B)  -- this CTA's 32 Whh feature rows
//   hs  [16][1024]  float  ( 65536 B)  -- staged h_prev; reduction scratch
//                                         aliases this region after compute.
// Grid (32 ftiles) x (4 batch groups), 256 threads, 1 CTA/SM.
// ============================================================================
__global__ __launch_bounds__(256, 1)
void rnn_persistent(const float* __restrict__ h0,
                    const float* __restrict__ Whh,
                    const float* __restrict__ bias,
                    float* __restrict__ y,
                    float* __restrict__ hlast)
{
    extern __shared__ float smem[];
    float* wsm = smem;               // 32 * 1024
    float* hs  = smem + 32 * 1024;   // 16 * 1024
    float (*red)[32][33] = (float (*)[32][33])hs;   // 8*32*33 floats, aliases hs

    const int tid  = threadIdx.x;
    const int w    = tid >> 5;
    const int lane = tid & 31;
    const int ftile = blockIdx.x * 32;
    const int bg    = blockIdx.y * 16;
    const unsigned NB = gridDim.x * gridDim.y;   // 128

    // ---- one-time: load this CTA's Whh slice into smem ----
#pragma unroll 4
    for (int r = 0; r < 32; r++) {
        int slot = r * 256 + tid;        // 0..8191 float4 slots
        int f = slot >> 8;               // 0..31
        int c = (slot & 255) * 4;
        *(float4*)&wsm[f * 1024 + c] =
            *(const float4*)(Whh + (size_t)(ftile + f) * H_ + c);
    }
    // bias for the 64 outputs this warp produces (2 per pass)
    __syncthreads();

    for (int s = 0; s < S_; s++) {
        const float* hprev = (s == 0) ? h0 : (y + (size_t)(s - 1) * H_);
        const int hstride  = (s == 0) ? H_ : SH_;
        float* y_s = y + (size_t)s * H_;

        // ---- stage full h_prev[bg..bg+15][0..1023] in one burst ----
#pragma unroll
        for (int r = 0; r < 16; r++) {
            int slot = r * 256 + tid;    // 0..4095 float4 slots
            int b = slot >> 8;           // 0..15
            int c = (slot & 255) * 4;
            float4 v = __ldcg((const float4*)(hprev +
                       (size_t)(bg + b) * hstride + c));
            *(float4*)&hs[b * 1024 + c] = v;
        }
        __syncthreads();

        // ---- compute: 32 features x 16 batches, K lane-split ----
        ULL acc[4][16];
#pragma unroll
        for (int f = 0; f < 4; f++)
#pragma unroll
            for (int b = 0; b < 16; b++) acc[f][b] = 0ull;

#pragma unroll 1
        for (int chunk = 0; chunk < 8; chunk++) {
            const int kc = chunk * 128 + lane * 4;
            ulonglong2 w2[4];
#pragma unroll
            for (int f = 0; f < 4; f++)
                w2[f] = *(const ulonglong2*)&wsm[(w * 4 + f) * 1024 + kc];
#pragma unroll
            for (int b = 0; b < 16; b++) {
                ulonglong2 hv = *(const ulonglong2*)&hs[b * 1024 + kc];
#pragma unroll
                for (int f = 0; f < 4; f++) {
                    fma2(acc[f][b], hv.x, w2[f].x);
                    fma2(acc[f][b], hv.y, w2[f].y);
                }
            }
        }
        __syncthreads();   // hs reads done; red may now alias it

        // ---- reduce 32 lane K-slices; two passes of 32 outputs ----
#pragma unroll
        for (int p = 0; p < 2; p++) {
            __syncwarp();
#pragma unroll
            for (int fl = 0; fl < 2; fl++) {
                int f = p * 2 + fl;
#pragma unroll
                for (int b = 0; b < 16; b++)
                    red[w][fl * 16 + b][lane] = pairsum(acc[f][b]);
            }
            __syncwarp();
            float sum = 0.0f;
#pragma unroll
            for (int j = 0; j < 32; j++) sum += red[w][lane][j];

            const int o   = p * 32 + lane;     // 0..63
            const int fl  = o >> 4;            // p*2 + (lane>>4) local f
            const int bl  = o & 15;
            const int fg  = ftile + w * 4 + fl;
            const int bgl = bg + bl;
            float* yp = y_s + (size_t)bgl * SH_ + fg;
            float val = tanhf(*yp + sum + bias[fg]);
            *yp = val;
            if (s == S_ - 1) hlast[(size_t)bgl * H_ + fg] = val;
        }

        if (s < S_ - 1) grid_barrier(NB);
    }
}

// ============================================================================
// Launch: 2 graph nodes. Inputs: x, h, Wih_w, Wih_b, Whh_w, Whh_b.
// Output: y [B,S,H] followed by h_last [B,H].
// ============================================================================
extern "C" void kernel_launch(void* const* d_in, const int* in_sizes, int n_in,
                              void* d_out, int out_size)
{
    const float* x     = (const float*)d_in[0];
    const float* h0    = (const float*)d_in[1];
    const float* Wih_w = (const float*)d_in[2];
    const float* Wih_b = (const float*)d_in[3];
    const float* Whh_w = (const float*)d_in[4];
    const float* Whh_b = (const float*)d_in[5];

    float* y     = (float*)d_out;
    float* hlast = y + (size_t)B_ * S_ * H_;

    const int smem_bytes = (32 * 1024 + 16 * 1024) * sizeof(float);  // 196608
    cudaFuncSetAttribute(rnn_persistent,
                         cudaFuncAttributeMaxDynamicSharedMemorySize,
                         smem_bytes);

    wx_gemm<<<dim3(8, 512), 256>>>(x, Wih_w, Wih_b, y);
    rnn_persistent<<<dim3(32, 4), 256, smem_bytes>>>(h0, Whh_w, Whh_b, y, hlast);
}

// round 5
// speedup vs baseline: 1.2477x; 1.0421x over previous
#include <cuda_runtime.h>
#include <cstdint>

typedef unsigned long long ULL;

#define B_   64
#define S_   1024
#define I_   1024
#define H_   1024
#define SH_  (S_ * H_)   // 1048576

// ---- packed f32x2 helpers (B300 / sm_103a only) ----
__device__ __forceinline__ void fma2(ULL& d, ULL a, ULL b) {
    asm("fma.rn.f32x2 %0, %1, %2, %0;" : "+l"(d) : "l"(a), "l"(b));
}
__device__ __forceinline__ ULL dup2(float x) {
    ULL r;
    asm("mov.b64 %0, {%1, %1};" : "=l"(r) : "f"(x));
    return r;
}
__device__ __forceinline__ float pairsum(ULL v) {
    union { ULL u; float2 f; } t;
    t.u = v;
    return t.f.x + t.f.y;
}

// ============================================================================
// Kernel 1: wx[m, n] = sum_k x[m,k] * Wih[n,k] + Wih_b[n]   (unchanged)
// ============================================================================
__global__ __launch_bounds__(256, 2)
void wx_gemm(const float* __restrict__ A,
             const float* __restrict__ W,
             const float* __restrict__ bias,
             float* __restrict__ C)
{
    __shared__ float As[8][128];
    __shared__ float Bs[8][128];

    const int tid = threadIdx.x;
    const int m0 = blockIdx.y * 128;
    const int n0 = blockIdx.x * 128;

    const int lrow = tid >> 1;
    const int lk4  = (tid & 1) * 4;

    const float* Aptr = A + (size_t)(m0 + lrow) * I_ + lk4;
    const float* Wptr = W + (size_t)(n0 + lrow) * I_ + lk4;

    const int tx = tid & 15;
    const int ty = tid >> 4;

    ULL acc[8][4];
#pragma unroll
    for (int i = 0; i < 8; i++)
#pragma unroll
        for (int j = 0; j < 4; j++) acc[i][j] = 0ull;

    for (int k0 = 0; k0 < I_; k0 += 8) {
        float4 av = *(const float4*)(Aptr + k0);
        float4 wv = *(const float4*)(Wptr + k0);
        __syncthreads();
        As[lk4 + 0][lrow] = av.x;
        As[lk4 + 1][lrow] = av.y;
        As[lk4 + 2][lrow] = av.z;
        As[lk4 + 3][lrow] = av.w;
        Bs[lk4 + 0][lrow] = wv.x;
        Bs[lk4 + 1][lrow] = wv.y;
        Bs[lk4 + 2][lrow] = wv.z;
        Bs[lk4 + 3][lrow] = wv.w;
        __syncthreads();

#pragma unroll
        for (int kk = 0; kk < 8; kk++) {
            float4 a0 = *(const float4*)&As[kk][ty * 8];
            float4 a1 = *(const float4*)&As[kk][ty * 8 + 4];
            const ULL* bp = (const ULL*)&Bs[kk][tx * 8];
            ULL b2[4];
            b2[0] = bp[0]; b2[1] = bp[1]; b2[2] = bp[2]; b2[3] = bp[3];
            float a[8] = {a0.x, a0.y, a0.z, a0.w, a1.x, a1.y, a1.z, a1.w};
#pragma unroll
            for (int i = 0; i < 8; i++) {
                ULL ad = dup2(a[i]);
#pragma unroll
                for (int j = 0; j < 4; j++) fma2(acc[i][j], ad, b2[j]);
            }
        }
    }

    const float4* bp4 = (const float4*)(bias + n0 + tx * 8);
    float4 bv0 = bp4[0];
    float4 bv1 = bp4[1];
    float* Cp = C + (size_t)(m0 + ty * 8) * H_ + n0 + tx * 8;
#pragma unroll
    for (int i = 0; i < 8; i++) {
        union { ULL u; float2 f; } t0, t1, t2, t3;
        t0.u = acc[i][0]; t1.u = acc[i][1]; t2.u = acc[i][2]; t3.u = acc[i][3];
        float4 o0 = make_float4(t0.f.x + bv0.x, t0.f.y + bv0.y,
                                t1.f.x + bv0.z, t1.f.y + bv0.w);
        float4 o1 = make_float4(t2.f.x + bv1.x, t2.f.y + bv1.y,
                                t3.f.x + bv1.z, t3.f.y + bv1.w);
        *(float4*)(Cp + (size_t)i * H_)     = o0;
        *(float4*)(Cp + (size_t)i * H_ + 4) = o1;
    }
}

// ============================================================================
// Per-batch-group barrier: 4 independent 32-CTA barriers.
// Counters live on separate 128B lines. Generation is monotonic across
// graph replays. nanosleep backoff keeps L2 poll pressure low.
// ============================================================================
__device__ unsigned g_cnt[4 * 32];   // index bg*32
__device__ unsigned g_gen[4 * 32];

__device__ __forceinline__ void group_barrier(int bg, unsigned nb) {
    __syncthreads();
    if (threadIdx.x == 0) {
        unsigned* cnt = &g_cnt[bg * 32];
        unsigned* gen = &g_gen[bg * 32];
        unsigned g;
        asm volatile("ld.global.acquire.gpu.u32 %0, [%1];" : "=r"(g) : "l"(gen));
        unsigned prev;
        asm volatile("atom.global.release.gpu.add.u32 %0, [%1], %2;"
                     : "=r"(prev) : "l"(cnt), "r"(1u));
        if (prev == nb - 1) {
            asm volatile("st.global.relaxed.gpu.u32 [%0], %1;" :: "l"(cnt), "r"(0u));
            asm volatile("st.global.release.gpu.u32 [%0], %1;" :: "l"(gen), "r"(g + 1u));
        } else {
            unsigned cur;
            while (true) {
                asm volatile("ld.global.acquire.gpu.u32 %0, [%1];" : "=r"(cur) : "l"(gen));
                if (cur != g) break;
                __nanosleep(50);
            }
        }
    }
    __syncthreads();
}

// ============================================================================
// Kernel 2: persistent recurrence, Whh resident in smem, 8f x 8b warp tiles.
// Dynamic smem (196608 B):
//   wsm [32][1024] float (131072 B) -- CTA's 32 Whh feature rows
//   hs  [16][1024] float ( 65536 B) -- staged h_prev; reduction scratch
//                                      aliases this region after compute.
// Grid (32 ftiles) x (4 batch groups), 256 threads, 1 CTA/SM.
// Warp w: features ftile + (w&3)*8 .. +7,  batches bg + (w>>2)*8 .. +7.
// ============================================================================
__global__ __launch_bounds__(256, 1)
void rnn_persistent(const float* __restrict__ h0,
                    const float* __restrict__ Whh,
                    const float* __restrict__ bias,
                    float* __restrict__ y,
                    float* __restrict__ hlast)
{
    extern __shared__ float smem[];
    float* wsm = smem;               // 32 * 1024
    float* hs  = smem + 32 * 1024;   // 16 * 1024
    float (*red)[32][33] = (float (*)[32][33])hs;   // aliases hs after compute

    const int tid  = threadIdx.x;
    const int w    = tid >> 5;
    const int lane = tid & 31;
    const int fw   = w & 3;          // feature sub-tile
    const int bw   = w >> 2;         // batch sub-tile
    const int ftile = blockIdx.x * 32;
    const int bg    = blockIdx.y * 16;

    // ---- one-time: load this CTA's Whh slice into smem ----
#pragma unroll 4
    for (int r = 0; r < 32; r++) {
        int slot = r * 256 + tid;        // 0..8191 float4 slots
        int f = slot >> 8;
        int c = (slot & 255) * 4;
        *(float4*)&wsm[f * 1024 + c] =
            *(const float4*)(Whh + (size_t)(ftile + f) * H_ + c);
    }

    // bias for this warp's 8 features, cached in registers
    float bias_r[8];
#pragma unroll
    for (int f = 0; f < 8; f++)
        bias_r[f] = bias[ftile + fw * 8 + f];

    __syncthreads();

    for (int s = 0; s < S_; s++) {
        const float* hprev = (s == 0) ? h0 : (y + (size_t)(s - 1) * H_);
        const int hstride  = (s == 0) ? H_ : SH_;
        float* y_s = y + (size_t)s * H_;

        // ---- stage h_prev[bg..bg+15][0..1023] in one high-MLP burst ----
#pragma unroll
        for (int r = 0; r < 16; r++) {
            int slot = r * 256 + tid;    // 0..4095 float4 slots
            int b = slot >> 8;
            int c = (slot & 255) * 4;
            float4 v = __ldcg((const float4*)(hprev +
                       (size_t)(bg + b) * hstride + c));
            *(float4*)&hs[b * 1024 + c] = v;
        }
        __syncthreads();

        // ---- compute: 8 features x 8 batches per warp, K lane-split ----
        ULL acc[8][8];
#pragma unroll
        for (int f = 0; f < 8; f++)
#pragma unroll
            for (int b = 0; b < 8; b++) acc[f][b] = 0ull;

#pragma unroll 1
        for (int chunk = 0; chunk < 8; chunk++) {
            const int kc = chunk * 128 + lane * 4;
            ulonglong2 w2[8];
#pragma unroll
            for (int f = 0; f < 8; f++)
                w2[f] = *(const ulonglong2*)&wsm[(fw * 8 + f) * 1024 + kc];
#pragma unroll
            for (int b = 0; b < 8; b++) {
                ulonglong2 hv = *(const ulonglong2*)&hs[(bw * 8 + b) * 1024 + kc];
#pragma unroll
                for (int f = 0; f < 8; f++) {
                    fma2(acc[f][b], hv.x, w2[f].x);
                    fma2(acc[f][b], hv.y, w2[f].y);
                }
            }
        }
        __syncthreads();   // hs reads done; red may now alias it

        // ---- reduce 32 lane K-slices; two passes of 32 outputs ----
#pragma unroll
        for (int p = 0; p < 2; p++) {
            __syncwarp();
#pragma unroll
            for (int fl = 0; fl < 4; fl++) {
                int f = p * 4 + fl;
#pragma unroll
                for (int b = 0; b < 8; b++)
                    red[w][fl * 8 + b][lane] = pairsum(acc[f][b]);
            }
            __syncwarp();
            float sum = 0.0f;
#pragma unroll
            for (int j = 0; j < 32; j++) sum += red[w][lane][j];

            // lane o: fl = o>>3 (0..3), b = o&7
            const int fl  = lane >> 3;
            const int bl  = lane & 7;
            const int fg  = ftile + fw * 8 + p * 4 + fl;
            const int bgl = bg + bw * 8 + bl;
            float* yp = y_s + (size_t)bgl * SH_ + fg;
            float val = tanhf(*yp + sum + bias_r[p * 4 + fl]);
            *yp = val;
            if (s == S_ - 1) hlast[(size_t)bgl * H_ + fg] = val;
        }

        if (s < S_ - 1) group_barrier(blockIdx.y, gridDim.x);
    }
}

// ============================================================================
// Launch: 2 graph nodes. Inputs: x, h, Wih_w, Wih_b, Whh_w, Whh_b.
// Output: y [B,S,H] followed by h_last [B,H].
// ============================================================================
extern "C" void kernel_launch(void* const* d_in, const int* in_sizes, int n_in,
                              void* d_out, int out_size)
{
    const float* x     = (const float*)d_in[0];
    const float* h0    = (const float*)d_in[1];
    const float* Wih_w = (const float*)d_in[2];
    const float* Wih_b = (const float*)d_in[3];
    const float* Whh_w = (const float*)d_in[4];
    const float* Whh_b = (const float*)d_in[5];

    float* y     = (float*)d_out;
    float* hlast = y + (size_t)B_ * S_ * H_;

    const int smem_bytes = (32 * 1024 + 16 * 1024) * sizeof(float);  // 196608
    cudaFuncSetAttribute(rnn_persistent,
                         cudaFuncAttributeMaxDynamicSharedMemorySize,
                         smem_bytes);

    wx_gemm<<<dim3(8, 512), 256>>>(x, Wih_w, Wih_b, y);
    rnn_persistent<<<dim3(32, 4), 256, smem_bytes>>>(h0, Whh_w, Whh_b, y, hlast);
}

// round 6
// speedup vs baseline: 1.3912x; 1.1150x over previous
#include <cuda_runtime.h>
#include <cstdint>

typedef unsigned long long ULL;

#define B_   64
#define S_   1024
#define I_   1024
#define H_   1024
#define SH_  (S_ * H_)   // 1048576

// ---- packed f32x2 helpers (B300 / sm_103a only) ----
__device__ __forceinline__ void fma2(ULL& d, ULL a, ULL b) {
    asm("fma.rn.f32x2 %0, %1, %2, %0;" : "+l"(d) : "l"(a), "l"(b));
}
__device__ __forceinline__ ULL dup2(float x) {
    ULL r;
    asm("mov.b64 %0, {%1, %1};" : "=l"(r) : "f"(x));
    return r;
}
__device__ __forceinline__ float pairsum(ULL v) {
    union { ULL u; float2 f; } t;
    t.u = v;
    return t.f.x + t.f.y;
}
__device__ __forceinline__ void cp_async16(uint32_t smem_addr, const void* gptr) {
    asm volatile("cp.async.cg.shared.global [%0], [%1], 16;"
                 :: "r"(smem_addr), "l"(gptr));
}

// ============================================================================
// Kernel 1: wx[m, n] = sum_k x[m,k] * Wih[n,k] + Wih_b[n]   (unchanged)
// ============================================================================
__global__ __launch_bounds__(256, 2)
void wx_gemm(const float* __restrict__ A,
             const float* __restrict__ W,
             const float* __restrict__ bias,
             float* __restrict__ C)
{
    __shared__ float As[8][128];
    __shared__ float Bs[8][128];

    const int tid = threadIdx.x;
    const int m0 = blockIdx.y * 128;
    const int n0 = blockIdx.x * 128;

    const int lrow = tid >> 1;
    const int lk4  = (tid & 1) * 4;

    const float* Aptr = A + (size_t)(m0 + lrow) * I_ + lk4;
    const float* Wptr = W + (size_t)(n0 + lrow) * I_ + lk4;

    const int tx = tid & 15;
    const int ty = tid >> 4;

    ULL acc[8][4];
#pragma unroll
    for (int i = 0; i < 8; i++)
#pragma unroll
        for (int j = 0; j < 4; j++) acc[i][j] = 0ull;

    for (int k0 = 0; k0 < I_; k0 += 8) {
        float4 av = *(const float4*)(Aptr + k0);
        float4 wv = *(const float4*)(Wptr + k0);
        __syncthreads();
        As[lk4 + 0][lrow] = av.x;
        As[lk4 + 1][lrow] = av.y;
        As[lk4 + 2][lrow] = av.z;
        As[lk4 + 3][lrow] = av.w;
        Bs[lk4 + 0][lrow] = wv.x;
        Bs[lk4 + 1][lrow] = wv.y;
        Bs[lk4 + 2][lrow] = wv.z;
        Bs[lk4 + 3][lrow] = wv.w;
        __syncthreads();

#pragma unroll
        for (int kk = 0; kk < 8; kk++) {
            float4 a0 = *(const float4*)&As[kk][ty * 8];
            float4 a1 = *(const float4*)&As[kk][ty * 8 + 4];
            const ULL* bp = (const ULL*)&Bs[kk][tx * 8];
            ULL b2[4];
            b2[0] = bp[0]; b2[1] = bp[1]; b2[2] = bp[2]; b2[3] = bp[3];
            float a[8] = {a0.x, a0.y, a0.z, a0.w, a1.x, a1.y, a1.z, a1.w};
#pragma unroll
            for (int i = 0; i < 8; i++) {
                ULL ad = dup2(a[i]);
#pragma unroll
                for (int j = 0; j < 4; j++) fma2(acc[i][j], ad, b2[j]);
            }
        }
    }

    const float4* bp4 = (const float4*)(bias + n0 + tx * 8);
    float4 bv0 = bp4[0];
    float4 bv1 = bp4[1];
    float* Cp = C + (size_t)(m0 + ty * 8) * H_ + n0 + tx * 8;
#pragma unroll
    for (int i = 0; i < 8; i++) {
        union { ULL u; float2 f; } t0, t1, t2, t3;
        t0.u = acc[i][0]; t1.u = acc[i][1]; t2.u = acc[i][2]; t3.u = acc[i][3];
        float4 o0 = make_float4(t0.f.x + bv0.x, t0.f.y + bv0.y,
                                t1.f.x + bv0.z, t1.f.y + bv0.w);
        float4 o1 = make_float4(t2.f.x + bv1.x, t2.f.y + bv1.y,
                                t3.f.x + bv1.z, t3.f.y + bv1.w);
        *(float4*)(Cp + (size_t)i * H_)     = o0;
        *(float4*)(Cp + (size_t)i * H_ + 4) = o1;
    }
}

// ============================================================================
// Per-batch-group barrier: 4 independent 32-CTA barriers, separate lines.
// acq_rel arrival gives store->release->acquire transitivity for all arrivers.
// ============================================================================
__device__ unsigned g_cnt[4 * 32];
__device__ unsigned g_gen[4 * 32];

__device__ __forceinline__ void group_barrier(int bg, unsigned nb) {
    __syncthreads();
    if (threadIdx.x == 0) {
        unsigned* cnt = &g_cnt[bg * 32];
        unsigned* gen = &g_gen[bg * 32];
        unsigned g;
        asm volatile("ld.global.acquire.gpu.u32 %0, [%1];" : "=r"(g) : "l"(gen));
        unsigned prev;
        asm volatile("atom.global.acq_rel.gpu.add.u32 %0, [%1], %2;"
                     : "=r"(prev) : "l"(cnt), "r"(1u));
        if (prev == nb - 1) {
            asm volatile("st.global.relaxed.gpu.u32 [%0], %1;" :: "l"(cnt), "r"(0u));
            asm volatile("st.global.release.gpu.u32 [%0], %1;" :: "l"(gen), "r"(g + 1u));
        } else {
            unsigned cur;
            do {
                asm volatile("ld.global.acquire.gpu.u32 %0, [%1];" : "=r"(cur) : "l"(gen));
            } while (cur == g);
        }
    }
    __syncthreads();
}

// ============================================================================
// Kernel 2: persistent recurrence, Whh smem-resident, cp.async-pipelined
// h staging (4 chunks of 256 k), register-prefetched wx.
// smem: wsm 32x1024 (128KB) + hs 16x1024 (64KB, aliased by reduce scratch).
// Grid (32 ftiles) x (4 bgroups), 256 thr, 1 CTA/SM.
// Warp w: features ftile+(w&3)*8.., batches bg+(w>>2)*8..
// ============================================================================
__global__ __launch_bounds__(256, 1)
void rnn_persistent(const float* __restrict__ h0,
                    const float* __restrict__ Whh,
                    const float* __restrict__ bias,
                    float* __restrict__ y,
                    float* __restrict__ hlast)
{
    extern __shared__ float smem[];
    float* wsm = smem;               // 32 * 1024
    float* hs  = smem + 32 * 1024;   // 16 * 1024
    float (*red)[32][33] = (float (*)[32][33])hs;   // aliases hs after compute

    const int tid  = threadIdx.x;
    const int w    = tid >> 5;
    const int lane = tid & 31;
    const int fw   = w & 3;
    const int bw   = w >> 2;
    const int ftile = blockIdx.x * 32;
    const int bg    = blockIdx.y * 16;

    // ---- one-time: Whh slice into smem ----
#pragma unroll 4
    for (int r = 0; r < 32; r++) {
        int slot = r * 256 + tid;
        int f = slot >> 8;
        int c = (slot & 255) * 4;
        *(float4*)&wsm[f * 1024 + c] =
            *(const float4*)(Whh + (size_t)(ftile + f) * H_ + c);
    }

    // this thread's two outputs: p = 0,1
    const int fl  = lane >> 3;            // 0..3
    const int bl  = lane & 7;
    const int bgl = bg + bw * 8 + bl;
    const int fg0 = ftile + fw * 8 + 0 * 4 + fl;
    const int fg1 = ftile + fw * 8 + 1 * 4 + fl;
    float bias0 = bias[fg0];
    float bias1 = bias[fg1];
    float* yp0 = y + (size_t)bgl * SH_ + fg0;   // advance by H_ per step
    float* yp1 = y + (size_t)bgl * SH_ + fg1;

    const uint32_t hs_base = (uint32_t)__cvta_generic_to_shared(hs);

    // prefetch wx for step 0
    float wx0 = yp0[0];
    float wx1 = yp1[0];

    __syncthreads();

    for (int s = 0; s < S_; s++) {
        const float* hprev = (s == 0) ? h0 : (y + (size_t)(s - 1) * H_);
        const int hstride  = (s == 0) ? H_ : SH_;

        // ---- issue all staging cp.asyncs, 4 committed groups of 16KB ----
#pragma unroll
        for (int c = 0; c < 4; c++) {
#pragma unroll
            for (int r = 0; r < 4; r++) {
                int idx = r * 256 + tid;          // 0..1023 float4 slots
                int b   = idx >> 6;               // 0..15
                int c4  = (idx & 63) << 2;        // 0..252
                const float* gp = hprev + (size_t)(bg + b) * hstride + c * 256 + c4;
                cp_async16(hs_base + (uint32_t)(b * 1024 + c * 256 + c4) * 4u, gp);
            }
            asm volatile("cp.async.commit_group;" ::: "memory");
        }

        // ---- pipelined compute: consume chunk c while c+1.. in flight ----
        ULL acc[8][8];
#pragma unroll
        for (int f = 0; f < 8; f++)
#pragma unroll
            for (int b = 0; b < 8; b++) acc[f][b] = 0ull;

#pragma unroll
        for (int c = 0; c < 4; c++) {
            if      (c == 0) asm volatile("cp.async.wait_group 3;" ::: "memory");
            else if (c == 1) asm volatile("cp.async.wait_group 2;" ::: "memory");
            else if (c == 2) asm volatile("cp.async.wait_group 1;" ::: "memory");
            else             asm volatile("cp.async.wait_group 0;" ::: "memory");
            __syncthreads();

#pragma unroll
            for (int half = 0; half < 2; half++) {
                const int kc = c * 256 + half * 128 + lane * 4;
                ulonglong2 w2[8];
#pragma unroll
                for (int f = 0; f < 8; f++)
                    w2[f] = *(const ulonglong2*)&wsm[(fw * 8 + f) * 1024 + kc];
#pragma unroll
                for (int b = 0; b < 8; b++) {
                    ulonglong2 hv = *(const ulonglong2*)&hs[(bw * 8 + b) * 1024 + kc];
#pragma unroll
                    for (int f = 0; f < 8; f++) {
                        fma2(acc[f][b], hv.x, w2[f].x);
                        fma2(acc[f][b], hv.y, w2[f].y);
                    }
                }
            }
        }
        __syncthreads();   // hs reads done; red may alias it

        // ---- reduce 32 lane K-slices; two passes of 32 outputs ----
        float* y_s0 = yp0 + (size_t)s * H_;
        float* y_s1 = yp1 + (size_t)s * H_;
#pragma unroll
        for (int p = 0; p < 2; p++) {
            __syncwarp();
#pragma unroll
            for (int ff = 0; ff < 4; ff++) {
                int f = p * 4 + ff;
#pragma unroll
                for (int b = 0; b < 8; b++)
                    red[w][ff * 8 + b][lane] = pairsum(acc[f][b]);
            }
            __syncwarp();
            float sum = 0.0f;
#pragma unroll
            for (int j = 0; j < 32; j++) sum += red[w][lane][j];

            if (p == 0) {
                float val = tanhf(wx0 + sum + bias0);
                *y_s0 = val;
                if (s == S_ - 1) hlast[(size_t)bgl * H_ + fg0] = val;
            } else {
                float val = tanhf(wx1 + sum + bias1);
                *y_s1 = val;
                if (s == S_ - 1) hlast[(size_t)bgl * H_ + fg1] = val;
            }
        }

        // prefetch next step's wx; overlaps the barrier wait
        if (s < S_ - 1) {
            wx0 = y_s0[H_];
            wx1 = y_s1[H_];
            group_barrier(blockIdx.y, gridDim.x);
        }
    }
}

// ============================================================================
// Launch: 2 graph nodes. Inputs: x, h, Wih_w, Wih_b, Whh_w, Whh_b.
// Output: y [B,S,H] followed by h_last [B,H].
// ============================================================================
extern "C" void kernel_launch(void* const* d_in, const int* in_sizes, int n_in,
                              void* d_out, int out_size)
{
    const float* x     = (const float*)d_in[0];
    const float* h0    = (const float*)d_in[1];
    const float* Wih_w = (const float*)d_in[2];
    const float* Wih_b = (const float*)d_in[3];
    const float* Whh_w = (const float*)d_in[4];
    const float* Whh_b = (const float*)d_in[5];

    float* y     = (float*)d_out;
    float* hlast = y + (size_t)B_ * S_ * H_;

    const int smem_bytes = (32 * 1024 + 16 * 1024) * sizeof(float);  // 196608
    cudaFuncSetAttribute(rnn_persistent,
                         cudaFuncAttributeMaxDynamicSharedMemorySize,
                         smem_bytes);

    wx_gemm<<<dim3(8, 512), 256>>>(x, Wih_w, Wih_b, y);
    rnn_persistent<<<dim3(32, 4), 256, smem_bytes>>>(h0, Whh_w, Whh_b, y, hlast);
}

// round 8
// speedup vs baseline: 1.6753x; 1.2041x over previous
#include <cuda_runtime.h>
#include <cstdint>

typedef unsigned long long ULL;

#define B_   64
#define S_   1024
#define I_   1024
#define H_   1024
#define SH_  (S_ * H_)   // 1048576

// ---- packed f32x2 helpers ----
__device__ __forceinline__ void fma2(ULL& d, ULL a, ULL b) {
    asm("fma.rn.f32x2 %0, %1, %2, %0;" : "+l"(d) : "l"(a), "l"(b));
}
__device__ __forceinline__ float pairsum(ULL v) {
    union { ULL u; float2 f; } t;
    t.u = v;
    return t.f.x + t.f.y;
}
__device__ __forceinline__ void cp_async16(uint32_t smem_addr, const void* gptr) {
    asm volatile("cp.async.cg.shared.global [%0], [%1], 16;"
                 :: "r"(smem_addr), "l"(gptr));
}
__device__ __forceinline__ uint32_t smem_u32(const void* p) {
    return (uint32_t)__cvta_generic_to_shared(p);
}
// pack: low half = bf16(v0), high half = bf16(v1)
__device__ __forceinline__ uint32_t pack_bf16(float v0, float v1) {
    uint32_t r;
    asm("cvt.rn.bf16x2.f32 %0, %1, %2;" : "=r"(r) : "f"(v1), "f"(v0));
    return r;
}

// ============================================================================
// Static scratch: split-bf16 copies of x and Wih (u32 = 2 packed bf16).
// ============================================================================
__device__ unsigned g_xhi[33554432];   // 64M bf16 = 128 MB
__device__ unsigned g_xlo[33554432];
__device__ unsigned g_whi[524288];     // 1M bf16
__device__ unsigned g_wlo[524288];

// ============================================================================
// Convert fp32 -> (hi, lo) bf16 pairs. which: 0 = x, 1 = W.
// ============================================================================
__global__ void cvt_split(const float* __restrict__ src, int which, int n4)
{
    unsigned* hi = which ? g_whi : g_xhi;
    unsigned* lo = which ? g_wlo : g_xlo;
    int stride = gridDim.x * blockDim.x;
    for (int i = blockIdx.x * blockDim.x + threadIdx.x; i < n4; i += stride) {
        float4 v = ((const float4*)src)[i];
        uint32_t h0 = pack_bf16(v.x, v.y);
        uint32_t h1 = pack_bf16(v.z, v.w);
        float l0 = v.x - __uint_as_float(h0 << 16);
        float l1 = v.y - __uint_as_float(h0 & 0xFFFF0000u);
        float l2 = v.z - __uint_as_float(h1 << 16);
        float l3 = v.w - __uint_as_float(h1 & 0xFFFF0000u);
        hi[2 * i]     = h0;
        hi[2 * i + 1] = h1;
        lo[2 * i]     = pack_bf16(l0, l1);
        lo[2 * i + 1] = pack_bf16(l2, l3);
    }
}

// ============================================================================
// wx_mma: y[m,n] = sum_k x[m,k] * Wih[n,k] + bias[n] via split-bf16 HMMA.
// CTA tile 128m x 64n, BK=32, 256 thr (8 warps, 4m x 2n, warp tile 32x32).
// Smem per stage: Ahi/Alo 128x32 bf16 (rows padded to 80 B), Bhi/Blo 64x32.
// Stage = 30720 B, double-buffered = 61440 B. cp.async from g_x*/g_w*.
// ============================================================================
#define STG_BYTES 30720
#define A_LO_OFF  10240
#define B_OFF     20480
#define B_LO_OFF  25600

__device__ __forceinline__ void mma_bf16(float& c0, float& c1, float& c2, float& c3,
                                         uint32_t a0, uint32_t a1, uint32_t a2, uint32_t a3,
                                         uint32_t b0, uint32_t b1) {
    asm volatile("mma.sync.aligned.m16n8k16.row.col.f32.bf16.bf16.f32 "
                 "{%0,%1,%2,%3}, {%4,%5,%6,%7}, {%8,%9}, {%0,%1,%2,%3};"
                 : "+f"(c0), "+f"(c1), "+f"(c2), "+f"(c3)
                 : "r"(a0), "r"(a1), "r"(a2), "r"(a3), "r"(b0), "r"(b1));
}

__global__ __launch_bounds__(256, 2)
void wx_mma(const float* __restrict__ bias, float* __restrict__ y)
{
    extern __shared__ __align__(16) char smem[];
    const uint32_t sbase = smem_u32(smem);

    const int tid  = threadIdx.x;
    const int wid  = tid >> 5;
    const int lane = tid & 31;
    const int g    = lane >> 2;       // group id 0..7
    const int t    = lane & 3;        // thread-in-group
    const int wm   = wid & 3;         // m warp 0..3
    const int wn   = wid >> 2;        // n warp 0..1
    const int m0   = blockIdx.y * 128;
    const int n0   = blockIdx.x * 64;

    float acc[2][4][4];
#pragma unroll
    for (int mf = 0; mf < 2; mf++)
#pragma unroll
        for (int nf = 0; nf < 4; nf++)
#pragma unroll
            for (int c = 0; c < 4; c++) acc[mf][nf][c] = 0.0f;

    // -------- staging lambda: issue cp.asyncs for K-chunk 'st' --------
    auto issue = [&](int st) {
        const uint32_t d = sbase + (st & 1) * STG_BYTES;
        const int k0 = st * 32;
        // A: 1024 x 16B tasks (hi then lo)
#pragma unroll
        for (int r = 0; r < 4; r++) {
            int id   = tid + 256 * r;
            int part = id >> 9;
            int rem  = id & 511;
            int row  = rem >> 2;
            int seg  = rem & 3;
            const unsigned* srcb = part ? g_xlo : g_xhi;
            const char* src = (const char*)(srcb +
                ((size_t)(m0 + row) * 1024 + k0) / 2) + seg * 16;
            cp_async16(d + part * A_LO_OFF + row * 80 + seg * 16, src);
        }
        // B: 512 x 16B tasks
#pragma unroll
        for (int r = 0; r < 2; r++) {
            int id   = tid + 256 * r;
            int part = id >> 8;
            int rem  = id & 255;
            int row  = rem >> 2;
            int seg  = rem & 3;
            const unsigned* srcb = part ? g_wlo : g_whi;
            const char* src = (const char*)(srcb +
                ((size_t)(n0 + row) * 1024 + k0) / 2) + seg * 16;
            cp_async16(d + B_OFF + part * 5120 + row * 80 + seg * 16, src);
        }
        asm volatile("cp.async.commit_group;" ::: "memory");
    };

    issue(0);
    for (int i = 0; i < 32; i++) {
        if (i + 1 < 32) {
            issue(i + 1);
            asm volatile("cp.async.wait_group 1;" ::: "memory");
        } else {
            asm volatile("cp.async.wait_group 0;" ::: "memory");
        }
        __syncthreads();

        const char* sm  = smem + (i & 1) * STG_BYTES;
        const char* Ahi = sm;
        const char* Alo = sm + A_LO_OFF;
        const char* Bhi = sm + B_OFF;
        const char* Blo = sm + B_LO_OFF;

#pragma unroll
        for (int ks = 0; ks < 32; ks += 16) {
            const int colb = (ks + t * 2) * 2;   // byte offset in row
            uint32_t ah[2][4], al[2][4];
#pragma unroll
            for (int mf = 0; mf < 2; mf++) {
                int r0 = (wm * 32 + mf * 16 + g) * 80;
                int r1 = r0 + 8 * 80;
                ah[mf][0] = *(const uint32_t*)(Ahi + r0 + colb);
                ah[mf][1] = *(const uint32_t*)(Ahi + r1 + colb);
                ah[mf][2] = *(const uint32_t*)(Ahi + r0 + colb + 16);
                ah[mf][3] = *(const uint32_t*)(Ahi + r1 + colb + 16);
                al[mf][0] = *(const uint32_t*)(Alo + r0 + colb);
                al[mf][1] = *(const uint32_t*)(Alo + r1 + colb);
                al[mf][2] = *(const uint32_t*)(Alo + r0 + colb + 16);
                al[mf][3] = *(const uint32_t*)(Alo + r1 + colb + 16);
            }
            uint32_t bh[4][2], bl[4][2];
#pragma unroll
            for (int nf = 0; nf < 4; nf++) {
                int nr = (wn * 32 + nf * 8 + g) * 80;
                bh[nf][0] = *(const uint32_t*)(Bhi + nr + colb);
                bh[nf][1] = *(const uint32_t*)(Bhi + nr + colb + 16);
                bl[nf][0] = *(const uint32_t*)(Blo + nr + colb);
                bl[nf][1] = *(const uint32_t*)(Blo + nr + colb + 16);
            }
#pragma unroll
            for (int mf = 0; mf < 2; mf++)
#pragma unroll
                for (int nf = 0; nf < 4; nf++) {
                    float* c = acc[mf][nf];
                    mma_bf16(c[0], c[1], c[2], c[3],
                             ah[mf][0], ah[mf][1], ah[mf][2], ah[mf][3],
                             bh[nf][0], bh[nf][1]);
                    mma_bf16(c[0], c[1], c[2], c[3],
                             al[mf][0], al[mf][1], al[mf][2], al[mf][3],
                             bh[nf][0], bh[nf][1]);
                    mma_bf16(c[0], c[1], c[2], c[3],
                             ah[mf][0], ah[mf][1], ah[mf][2], ah[mf][3],
                             bl[nf][0], bl[nf][1]);
                }
        }
        __syncthreads();
    }

    // -------- epilogue: add bias, write y --------
#pragma unroll
    for (int mf = 0; mf < 2; mf++) {
        int m = m0 + wm * 32 + mf * 16 + g;
#pragma unroll
        for (int nf = 0; nf < 4; nf++) {
            int n = n0 + wn * 32 + nf * 8 + t * 2;
            float2 bv = *(const float2*)(bias + n);
            float* c = acc[mf][nf];
            *(float2*)(y + (size_t)m * H_ + n) =
                make_float2(c[0] + bv.x, c[1] + bv.y);
            *(float2*)(y + (size_t)(m + 8) * H_ + n) =
                make_float2(c[2] + bv.x, c[3] + bv.y);
        }
    }
}

// ============================================================================
// Per-batch-group barrier: 4 independent 32-CTA barriers (unchanged).
// ============================================================================
__device__ unsigned g_cnt[4 * 32];
__device__ unsigned g_gen[4 * 32];

__device__ __forceinline__ void group_barrier(int bg, unsigned nb) {
    __syncthreads();
    if (threadIdx.x == 0) {
        unsigned* cnt = &g_cnt[bg * 32];
        unsigned* gen = &g_gen[bg * 32];
        unsigned g;
        asm volatile("ld.global.acquire.gpu.u32 %0, [%1];" : "=r"(g) : "l"(gen));
        unsigned prev;
        asm volatile("atom.global.acq_rel.gpu.add.u32 %0, [%1], %2;"
                     : "=r"(prev) : "l"(cnt), "r"(1u));
        if (prev == nb - 1) {
            asm volatile("st.global.relaxed.gpu.u32 [%0], %1;" :: "l"(cnt), "r"(0u));
            asm volatile("st.global.release.gpu.u32 [%0], %1;" :: "l"(gen), "r"(g + 1u));
        } else {
            unsigned cur;
            do {
                asm volatile("ld.global.acquire.gpu.u32 %0, [%1];" : "=r"(cur) : "l"(gen));
            } while (cur == g);
        }
    }
    __syncthreads();
}

// ============================================================================
// Persistent recurrence (unchanged from R6).
// ============================================================================
__global__ __launch_bounds__(256, 1)
void rnn_persistent(const float* __restrict__ h0,
                    const float* __restrict__ Whh,
                    const float* __restrict__ bias,
                    float* __restrict__ y,
                    float* __restrict__ hlast)
{
    extern __shared__ float smemf[];
    float* wsm = smemf;
    float* hs  = smemf + 32 * 1024;
    float (*red)[32][33] = (float (*)[32][33])hs;

    const int tid  = threadIdx.x;
    const int w    = tid >> 5;
    const int lane = tid & 31;
    const int fw   = w & 3;
    const int bw   = w >> 2;
    const int ftile = blockIdx.x * 32;
    const int bg    = blockIdx.y * 16;

#pragma unroll 4
    for (int r = 0; r < 32; r++) {
        int slot = r * 256 + tid;
        int f = slot >> 8;
        int c = (slot & 255) * 4;
        *(float4*)&wsm[f * 1024 + c] =
            *(const float4*)(Whh + (size_t)(ftile + f) * H_ + c);
    }

    const int fl  = lane >> 3;
    const int bl  = lane & 7;
    const int bgl = bg + bw * 8 + bl;
    const int fg0 = ftile + fw * 8 + 0 * 4 + fl;
    const int fg1 = ftile + fw * 8 + 1 * 4 + fl;
    float bias0 = bias[fg0];
    float bias1 = bias[fg1];
    float* yp0 = y + (size_t)bgl * SH_ + fg0;
    float* yp1 = y + (size_t)bgl * SH_ + fg1;

    const uint32_t hs_base = smem_u32(hs);

    float wx0 = yp0[0];
    float wx1 = yp1[0];

    __syncthreads();

    for (int s = 0; s < S_; s++) {
        const float* hprev = (s == 0) ? h0 : (y + (size_t)(s - 1) * H_);
        const int hstride  = (s == 0) ? H_ : SH_;

#pragma unroll
        for (int c = 0; c < 4; c++) {
#pragma unroll
            for (int r = 0; r < 4; r++) {
                int idx = r * 256 + tid;
                int b   = idx >> 6;
                int c4  = (idx & 63) << 2;
                const float* gp = hprev + (size_t)(bg + b) * hstride + c * 256 + c4;
                cp_async16(hs_base + (uint32_t)(b * 1024 + c * 256 + c4) * 4u, gp);
            }
            asm volatile("cp.async.commit_group;" ::: "memory");
        }

        ULL acc[8][8];
#pragma unroll
        for (int f = 0; f < 8; f++)
#pragma unroll
            for (int b = 0; b < 8; b++) acc[f][b] = 0ull;

#pragma unroll
        for (int c = 0; c < 4; c++) {
            if      (c == 0) asm volatile("cp.async.wait_group 3;" ::: "memory");
            else if (c == 1) asm volatile("cp.async.wait_group 2;" ::: "memory");
            else if (c == 2) asm volatile("cp.async.wait_group 1;" ::: "memory");
            else             asm volatile("cp.async.wait_group 0;" ::: "memory");
            __syncthreads();

#pragma unroll
            for (int half = 0; half < 2; half++) {
                const int kc = c * 256 + half * 128 + lane * 4;
                ulonglong2 w2[8];
#pragma unroll
                for (int f = 0; f < 8; f++)
                    w2[f] = *(const ulonglong2*)&wsm[(fw * 8 + f) * 1024 + kc];
#pragma unroll
                for (int b = 0; b < 8; b++) {
                    ulonglong2 hv = *(const ulonglong2*)&hs[(bw * 8 + b) * 1024 + kc];
#pragma unroll
                    for (int f = 0; f < 8; f++) {
                        fma2(acc[f][b], hv.x, w2[f].x);
                        fma2(acc[f][b], hv.y, w2[f].y);
                    }
                }
            }
        }
        __syncthreads();

        float* y_s0 = yp0 + (size_t)s * H_;
        float* y_s1 = yp1 + (size_t)s * H_;
#pragma unroll
        for (int p = 0; p < 2; p++) {
            __syncwarp();
#pragma unroll
            for (int ff = 0; ff < 4; ff++) {
                int f = p * 4 + ff;
#pragma unroll
                for (int b = 0; b < 8; b++)
                    red[w][ff * 8 + b][lane] = pairsum(acc[f][b]);
            }
            __syncwarp();
            float sum = 0.0f;
#pragma unroll
            for (int j = 0; j < 32; j++) sum += red[w][lane][j];

            if (p == 0) {
                float val = tanhf(wx0 + sum + bias0);
                *y_s0 = val;
                if (s == S_ - 1) hlast[(size_t)bgl * H_ + fg0] = val;
            } else {
                float val = tanhf(wx1 + sum + bias1);
                *y_s1 = val;
                if (s == S_ - 1) hlast[(size_t)bgl * H_ + fg1] = val;
            }
        }

        if (s < S_ - 1) {
            wx0 = y_s0[H_];
            wx1 = y_s1[H_];
            group_barrier(blockIdx.y, gridDim.x);
        }
    }
}

// ============================================================================
// Launch: 4 graph nodes. Inputs: x, h, Wih_w, Wih_b, Whh_w, Whh_b.
// Output: y [B,S,H] followed by h_last [B,H].
// ============================================================================
extern "C" void kernel_launch(void* const* d_in, const int* in_sizes, int n_in,
                              void* d_out, int out_size)
{
    const float* x     = (const float*)d_in[0];
    const float* h0    = (const float*)d_in[1];
    const float* Wih_w = (const float*)d_in[2];
    const float* Wih_b = (const float*)d_in[3];
    const float* Whh_w = (const float*)d_in[4];
    const float* Whh_b = (const float*)d_in[5];

    float* y     = (float*)d_out;
    float* hlast = y + (size_t)B_ * S_ * H_;

    const int mma_smem = 2 * STG_BYTES;   // 61440
    cudaFuncSetAttribute(wx_mma, cudaFuncAttributeMaxDynamicSharedMemorySize,
                         mma_smem);
    const int rnn_smem = (32 * 1024 + 16 * 1024) * sizeof(float);  // 196608
    cudaFuncSetAttribute(rnn_persistent,
                         cudaFuncAttributeMaxDynamicSharedMemorySize, rnn_smem);

    cvt_split<<<8192, 256>>>(x, 0, 16777216);      // x: 16M float4
    cvt_split<<<1024, 256>>>(Wih_w, 1, 262144);    // W: 256K float4
    wx_mma<<<dim3(16, 512), 256, mma_smem>>>(Wih_b, y);
    rnn_persistent<<<dim3(32, 4), 256, rnn_smem>>>(h0, Whh_w, Whh_b, y, hlast);
}